// round 15
// baseline (speedup 1.0000x reference)
#include <cuda_runtime.h>
#include <cuda_bf16.h>

// Problem constants
#define B_    2048
#define CELL_ 512
#define K_    30
#define L_    1024
#define V_    80
#define P_    90      // 3*K
#define NWARP 8
#define THREADS (NWARP*32)   // 256
#define RB    4              // batch rows per CTA in kernel A1
#define TCUT  32.0f          // exp(-32) ~ 1.3e-14: truncation threshold

// Scratch for alpha/beta between A1 and B (static device arrays are allowed)
__device__ float g_alpha[B_ * K_];
__device__ float g_beta [B_ * K_];

// ============================================================================
// Kernel A1: params = exp(x@W.T + b)  -> g_alpha, g_beta, kappa -> out
// k-triple structure: one x pass feeds (alpha_k, beta_k, kappa_k) dot products
// -> 3x fewer smem x re-reads (smem crossbar was the binding term at ~12us).
// ============================================================================
__global__ __launch_bounds__(THREADS, 4)
void params_kernel(const float* __restrict__ x,
                   const float* __restrict__ kappa_old,
                   const float* __restrict__ W,
                   const float* __restrict__ bias,
                   float* __restrict__ out)
{
    const int b0   = blockIdx.x * RB;
    const int tid  = threadIdx.x;
    const int lane = tid & 31;
    const int warp = tid >> 5;

    __shared__ float xs[RB][CELL_];

    // ---- load RB x-rows into smem (contiguous, vectorized) ----
    {
        const float4* xrow4 = (const float4*)(x + (size_t)b0 * CELL_);
        float4* xs4 = (float4*)&xs[0][0];
        for (int i = tid; i < RB * CELL_ / 4; i += THREADS) xs4[i] = xrow4[i];
    }
    __syncthreads();

    // ---- warp handles k = warp, warp+8, ...; rows of W for alpha_k (k),
    //      beta_k (k+30), kappa_k (k+60) consumed in ONE pass over x ----
    for (int k = warp; k < K_; k += NWARP) {
        const float4* Wa4 = (const float4*)(W + (size_t)(k         ) * CELL_);
        const float4* Wb4 = (const float4*)(W + (size_t)(k +     K_) * CELL_);
        const float4* Wk4 = (const float4*)(W + (size_t)(k + 2 * K_) * CELL_);
        // 12 scalar accumulators: [param a/b/k][row 0..3]
        float a0 = 0.f, a1 = 0.f, a2 = 0.f, a3 = 0.f;
        float e0 = 0.f, e1 = 0.f, e2 = 0.f, e3 = 0.f;
        float q0 = 0.f, q1 = 0.f, q2 = 0.f, q3 = 0.f;
        #pragma unroll
        for (int c = lane; c < CELL_ / 4; c += 32) {
            float4 wa = Wa4[c];
            float4 wb = Wb4[c];
            float4 wk = Wk4[c];
            float4 x0 = ((const float4*)xs[0])[c];
            float4 x1 = ((const float4*)xs[1])[c];
            float4 x2 = ((const float4*)xs[2])[c];
            float4 x3 = ((const float4*)xs[3])[c];
            a0 += wa.x * x0.x + wa.y * x0.y + wa.z * x0.z + wa.w * x0.w;
            a1 += wa.x * x1.x + wa.y * x1.y + wa.z * x1.z + wa.w * x1.w;
            a2 += wa.x * x2.x + wa.y * x2.y + wa.z * x2.z + wa.w * x2.w;
            a3 += wa.x * x3.x + wa.y * x3.y + wa.z * x3.z + wa.w * x3.w;
            e0 += wb.x * x0.x + wb.y * x0.y + wb.z * x0.z + wb.w * x0.w;
            e1 += wb.x * x1.x + wb.y * x1.y + wb.z * x1.z + wb.w * x1.w;
            e2 += wb.x * x2.x + wb.y * x2.y + wb.z * x2.z + wb.w * x2.w;
            e3 += wb.x * x3.x + wb.y * x3.y + wb.z * x3.z + wb.w * x3.w;
            q0 += wk.x * x0.x + wk.y * x0.y + wk.z * x0.z + wk.w * x0.w;
            q1 += wk.x * x1.x + wk.y * x1.y + wk.z * x1.z + wk.w * x1.w;
            q2 += wk.x * x2.x + wk.y * x2.y + wk.z * x2.z + wk.w * x2.w;
            q3 += wk.x * x3.x + wk.y * x3.y + wk.z * x3.z + wk.w * x3.w;
        }
        #pragma unroll
        for (int o = 16; o; o >>= 1) {
            a0 += __shfl_xor_sync(0xffffffffu, a0, o);
            a1 += __shfl_xor_sync(0xffffffffu, a1, o);
            a2 += __shfl_xor_sync(0xffffffffu, a2, o);
            a3 += __shfl_xor_sync(0xffffffffu, a3, o);
            e0 += __shfl_xor_sync(0xffffffffu, e0, o);
            e1 += __shfl_xor_sync(0xffffffffu, e1, o);
            e2 += __shfl_xor_sync(0xffffffffu, e2, o);
            e3 += __shfl_xor_sync(0xffffffffu, e3, o);
            q0 += __shfl_xor_sync(0xffffffffu, q0, o);
            q1 += __shfl_xor_sync(0xffffffffu, q1, o);
            q2 += __shfl_xor_sync(0xffffffffu, q2, o);
            q3 += __shfl_xor_sync(0xffffffffu, q3, o);
        }
        if (lane == 0) {
            const float ba = bias[k];
            const float bb = bias[k + K_];
            const float bk = bias[k + 2 * K_];
            float av[RB] = {a0, a1, a2, a3};
            float ev[RB] = {e0, e1, e2, e3};
            float qv[RB] = {q0, q1, q2, q3};
            #pragma unroll
            for (int r = 0; r < RB; r++) {
                size_t idx = (size_t)(b0 + r) * K_ + k;
                g_alpha[idx] = __expf(av[r] + ba);
                g_beta [idx] = __expf(ev[r] + bb);
                out[(size_t)B_ * V_ + idx] = kappa_old[idx] + __expf(qv[r] + bk);
            }
        }
    }
}

// ============================================================================
// Kernel B (fused): phi compute (truncated) + w contraction (HBM stream)
// ============================================================================
__global__ __launch_bounds__(THREADS, 8)
void contract_kernel(const float* __restrict__ oh,
                     const float* __restrict__ tlen,
                     float* out)
{
    const int b    = blockIdx.x;
    const int tid  = threadIdx.x;
    const int lane = tid & 31;
    const int warp = tid >> 5;

    __shared__ float  phi_s[L_];
    __shared__ float  alpha_s[K_], beta_s[K_], kappa_s[K_];
    __shared__ float  hi_max;
    __shared__ float4 red[NWARP * 20];

    // ---- fetch params (kappa was written to out by A1) ----
    if (tid < K_) {
        alpha_s[tid] = g_alpha[(size_t)b * K_ + tid];
        beta_s[tid]  = g_beta [(size_t)b * K_ + tid];
        kappa_s[tid] = out[(size_t)B_ * V_ + (size_t)b * K_ + tid];
    }
    __syncthreads();

    // ---- Gaussian support bound ----
    if (tid < 32) {
        float hi = 0.f;
        if (tid < K_)
            hi = kappa_s[tid] + sqrtf(TCUT / beta_s[tid]) + 1.0f;
        #pragma unroll
        for (int o = 16; o; o >>= 1) hi = fmaxf(hi, __shfl_xor_sync(0xffffffffu, hi, o));
        if (tid == 0) hi_max = hi;
    }
    __syncthreads();

    // ---- phi[l]: compute into smem AND write the phi output ----
    {
        const float scale = (float)L_ / tlen[b];
        const float mh = hi_max;
        float* phi_out = out + (size_t)B_ * V_ + (size_t)B_ * K_ + (size_t)b * (L_ + 1);
        for (int l = tid; l <= L_; l += THREADS) {
            const float fl = (float)l;
            float s = 0.f;
            if (fl <= mh) {     // warp-uniform for nearly all warps
                #pragma unroll 6
                for (int k = 0; k < K_; k++) {
                    float d = kappa_s[k] - fl;
                    s += alpha_s[k] * __expf(-beta_s[k] * d * d);
                }
                s *= scale;
            }
            if (l < L_) phi_s[l] = s;
            phi_out[l] = s;
        }
    }
    __syncthreads();

    // ---- w[v] = sum_{l<L} phi[l] * oh[b][l][v] ----
    // One row = 80 floats = 20 float4. Lanes 0..19 fetch a whole row as
    // LDG.128; warp-strided over l, unrolled x4 with front-batched loads.
    if (lane < 20) {
        const float4* base = (const float4*)(oh + (size_t)b * L_ * V_) + lane;
        float4 acc = make_float4(0.f, 0.f, 0.f, 0.f);
        for (int l0 = warp; l0 < L_; l0 += NWARP * 4) {
            float4 r0 = base[(size_t)(l0            ) * 20];
            float4 r1 = base[(size_t)(l0 +     NWARP) * 20];
            float4 r2 = base[(size_t)(l0 + 2 * NWARP) * 20];
            float4 r3 = base[(size_t)(l0 + 3 * NWARP) * 20];
            float p0 = phi_s[l0];
            float p1 = phi_s[l0 +     NWARP];
            float p2 = phi_s[l0 + 2 * NWARP];
            float p3 = phi_s[l0 + 3 * NWARP];
            acc.x += p0 * r0.x; acc.y += p0 * r0.y; acc.z += p0 * r0.z; acc.w += p0 * r0.w;
            acc.x += p1 * r1.x; acc.y += p1 * r1.y; acc.z += p1 * r1.z; acc.w += p1 * r1.w;
            acc.x += p2 * r2.x; acc.y += p2 * r2.y; acc.z += p2 * r2.z; acc.w += p2 * r2.w;
            acc.x += p3 * r3.x; acc.y += p3 * r3.y; acc.z += p3 * r3.z; acc.w += p3 * r3.w;
        }
        red[warp * 20 + lane] = acc;
    }
    __syncthreads();

    if (tid < V_) {
        const float* red_f = (const float*)red;
        float s = 0.f;
        #pragma unroll
        for (int w2 = 0; w2 < NWARP; w2++) s += red_f[w2 * V_ + tid];
        out[(size_t)b * V_ + tid] = s;   // w output
    }
}

extern "C" void kernel_launch(void* const* d_in, const int* in_sizes, int n_in,
                              void* d_out, int out_size)
{
    const float* x         = (const float*)d_in[0];   // [B, CELL]
    const float* kappa_old = (const float*)d_in[1];   // [B, K]
    const float* oh        = (const float*)d_in[2];   // [B, L, V]
    const float* tlen      = (const float*)d_in[3];   // [B, 1]
    const float* W         = (const float*)d_in[4];   // [3K, CELL]
    const float* bias      = (const float*)d_in[5];   // [3K]
    float* out             = (float*)d_out;           // [B*V | B*K | B*(L+1)]

    params_kernel<<<B_ / RB, THREADS>>>(x, kappa_old, W, bias, out);
    contract_kernel<<<B_, THREADS>>>(oh, tlen, out);
}

// round 16
// speedup vs baseline: 3.5742x; 3.5742x over previous
#include <cuda_runtime.h>
#include <cuda_bf16.h>

// Problem constants
#define B_    2048
#define CELL_ 512
#define K_    30
#define L_    1024
#define V_    80
#define P_    90      // 3*K
#define NWARP 8
#define THREADS (NWARP*32)   // 256
#define RB    4              // batch rows per CTA in kernel A1
#define TCUT  32.0f          // exp(-32) ~ 1.3e-14: truncation threshold

// Scratch for alpha/beta between A1 and B (static device arrays are allowed)
__device__ float g_alpha[B_ * K_];
__device__ float g_beta [B_ * K_];

// ============================================================================
// Kernel A1: params = exp(x@W.T + b)  -> g_alpha, g_beta, kappa -> out
// ============================================================================
__global__ __launch_bounds__(THREADS, 4)
void params_kernel(const float* __restrict__ x,
                   const float* __restrict__ kappa_old,
                   const float* __restrict__ W,
                   const float* __restrict__ bias,
                   float* __restrict__ out)
{
    const int b0   = blockIdx.x * RB;
    const int tid  = threadIdx.x;
    const int lane = tid & 31;
    const int warp = tid >> 5;

    __shared__ float xs[RB][CELL_];

    // ---- load RB x-rows into smem (contiguous, vectorized) ----
    {
        const float4* xrow4 = (const float4*)(x + (size_t)b0 * CELL_);
        float4* xs4 = (float4*)&xs[0][0];
        for (int i = tid; i < RB * CELL_ / 4; i += THREADS) xs4[i] = xrow4[i];
    }
    __syncthreads();

    // ---- warp w handles p = w, w+8, ...; each W load amortized over RB rows ----
    for (int p = warp; p < P_; p += NWARP) {
        const float4* Wr4 = (const float4*)(W + (size_t)p * CELL_);
        float s0 = 0.f, s1 = 0.f, s2 = 0.f, s3 = 0.f;
        #pragma unroll
        for (int c = lane; c < CELL_ / 4; c += 32) {
            float4 wv = Wr4[c];
            float4 x0 = ((const float4*)xs[0])[c];
            float4 x1 = ((const float4*)xs[1])[c];
            float4 x2 = ((const float4*)xs[2])[c];
            float4 x3 = ((const float4*)xs[3])[c];
            s0 += wv.x * x0.x + wv.y * x0.y + wv.z * x0.z + wv.w * x0.w;
            s1 += wv.x * x1.x + wv.y * x1.y + wv.z * x1.z + wv.w * x1.w;
            s2 += wv.x * x2.x + wv.y * x2.y + wv.z * x2.z + wv.w * x2.w;
            s3 += wv.x * x3.x + wv.y * x3.y + wv.z * x3.z + wv.w * x3.w;
        }
        #pragma unroll
        for (int o = 16; o; o >>= 1) {
            s0 += __shfl_xor_sync(0xffffffffu, s0, o);
            s1 += __shfl_xor_sync(0xffffffffu, s1, o);
            s2 += __shfl_xor_sync(0xffffffffu, s2, o);
            s3 += __shfl_xor_sync(0xffffffffu, s3, o);
        }
        if (lane == 0) {
            float sv[RB] = {s0, s1, s2, s3};
            const float bp = bias[p];
            #pragma unroll
            for (int r = 0; r < RB; r++) {
                float v = __expf(sv[r] + bp);
                if (p < K_) {
                    g_alpha[(size_t)(b0 + r) * K_ + p] = v;
                } else if (p < 2 * K_) {
                    g_beta[(size_t)(b0 + r) * K_ + (p - K_)] = v;
                } else {
                    int kk = p - 2 * K_;
                    float kap = kappa_old[(size_t)(b0 + r) * K_ + kk] + v;
                    out[(size_t)B_ * V_ + (size_t)(b0 + r) * K_ + kk] = kap;
                }
            }
        }
    }
}

// ============================================================================
// Kernel B (fused): phi compute (truncated) + w contraction over ONLY the
// Gaussian support rows (phi==0 beyond hi_max -> skip the DRAM stream there).
// ============================================================================
__global__ __launch_bounds__(THREADS, 8)
void contract_kernel(const float* __restrict__ oh,
                     const float* __restrict__ tlen,
                     float* out)
{
    const int b    = blockIdx.x;
    const int tid  = threadIdx.x;
    const int lane = tid & 31;
    const int warp = tid >> 5;

    __shared__ float  phi_s[L_];
    __shared__ float  alpha_s[K_], beta_s[K_], kappa_s[K_];
    __shared__ float  hi_max;
    __shared__ float4 red[NWARP * 20];

    // ---- fetch params (kappa was written to out by A1) ----
    if (tid < K_) {
        alpha_s[tid] = g_alpha[(size_t)b * K_ + tid];
        beta_s[tid]  = g_beta [(size_t)b * K_ + tid];
        kappa_s[tid] = out[(size_t)B_ * V_ + (size_t)b * K_ + tid];
    }
    __syncthreads();

    // ---- Gaussian support bound ----
    if (tid < 32) {
        float hi = 0.f;
        if (tid < K_)
            hi = kappa_s[tid] + sqrtf(TCUT / beta_s[tid]) + 1.0f;
        #pragma unroll
        for (int o = 16; o; o >>= 1) hi = fmaxf(hi, __shfl_xor_sync(0xffffffffu, hi, o));
        if (tid == 0) hi_max = hi;
    }
    __syncthreads();

    // ---- phi[l]: compute into smem AND write the phi output ----
    const float mh = hi_max;
    {
        const float scale = (float)L_ / tlen[b];
        float* phi_out = out + (size_t)B_ * V_ + (size_t)B_ * K_ + (size_t)b * (L_ + 1);
        for (int l = tid; l <= L_; l += THREADS) {
            const float fl = (float)l;
            float s = 0.f;
            if (fl <= mh) {     // warp-uniform for nearly all warps
                #pragma unroll 6
                for (int k = 0; k < K_; k++) {
                    float d = kappa_s[k] - fl;
                    s += alpha_s[k] * __expf(-beta_s[k] * d * d);
                }
                s *= scale;
            }
            if (l < L_) phi_s[l] = s;
            phi_out[l] = s;
        }
    }
    __syncthreads();

    // ---- number of rows actually carrying phi mass, padded to a multiple of
    //      32 (= NWARP*4) so the unrolled loop needs no remainder handling.
    //      phi_s is exactly 0 on [mh, nr), so the result is unchanged. ----
    int nr = (int)mh + 2;
    nr = (nr + 31) & ~31;
    if (nr > L_) nr = L_;

    // ---- w[v] = sum_{l<nr} phi[l] * oh[b][l][v] ----
    // One row = 80 floats = 20 float4. Lanes 0..19 fetch a whole row as
    // LDG.128; warp-strided over l, unrolled x4 with front-batched loads.
    if (lane < 20) {
        const float4* base = (const float4*)(oh + (size_t)b * L_ * V_) + lane;
        float4 acc = make_float4(0.f, 0.f, 0.f, 0.f);
        for (int l0 = warp; l0 < nr; l0 += NWARP * 4) {
            float4 r0 = base[(size_t)(l0            ) * 20];
            float4 r1 = base[(size_t)(l0 +     NWARP) * 20];
            float4 r2 = base[(size_t)(l0 + 2 * NWARP) * 20];
            float4 r3 = base[(size_t)(l0 + 3 * NWARP) * 20];
            float p0 = phi_s[l0];
            float p1 = phi_s[l0 +     NWARP];
            float p2 = phi_s[l0 + 2 * NWARP];
            float p3 = phi_s[l0 + 3 * NWARP];
            acc.x += p0 * r0.x; acc.y += p0 * r0.y; acc.z += p0 * r0.z; acc.w += p0 * r0.w;
            acc.x += p1 * r1.x; acc.y += p1 * r1.y; acc.z += p1 * r1.z; acc.w += p1 * r1.w;
            acc.x += p2 * r2.x; acc.y += p2 * r2.y; acc.z += p2 * r2.z; acc.w += p2 * r2.w;
            acc.x += p3 * r3.x; acc.y += p3 * r3.y; acc.z += p3 * r3.z; acc.w += p3 * r3.w;
        }
        red[warp * 20 + lane] = acc;
    }
    __syncthreads();

    if (tid < V_) {
        const float* red_f = (const float*)red;
        float s = 0.f;
        #pragma unroll
        for (int w2 = 0; w2 < NWARP; w2++) s += red_f[w2 * V_ + tid];
        out[(size_t)b * V_ + tid] = s;   // w output
    }
}

extern "C" void kernel_launch(void* const* d_in, const int* in_sizes, int n_in,
                              void* d_out, int out_size)
{
    const float* x         = (const float*)d_in[0];   // [B, CELL]
    const float* kappa_old = (const float*)d_in[1];   // [B, K]
    const float* oh        = (const float*)d_in[2];   // [B, L, V]
    const float* tlen      = (const float*)d_in[3];   // [B, 1]
    const float* W         = (const float*)d_in[4];   // [3K, CELL]
    const float* bias      = (const float*)d_in[5];   // [3K]
    float* out             = (float*)d_out;           // [B*V | B*K | B*(L+1)]

    params_kernel<<<B_ / RB, THREADS>>>(x, kappa_old, W, bias, out);
    contract_kernel<<<B_, THREADS>>>(oh, tlen, out);
}